// round 6
// baseline (speedup 1.0000x reference)
#include <cuda_runtime.h>
#include <cuda_bf16.h>
#include <cstdint>

// ---------------------------------------------------------------------------
// MedianConvolution: out[n,c] = lower_median_k( (x @ W^T)[nbrs[n,k], c] )
// N=100000, K=32, IN_C=128, OUT_C=64.  nbrs is int32 (JAX demotes int64).
// ---------------------------------------------------------------------------

#define N_NODES 100000
#define IN_C    128
#define OUT_C   64
#define KNBR    32

// intermediate h = x @ W^T  (25.6 MB static device scratch — allocation-free)
__device__ float g_h[N_NODES * OUT_C];

// ---------------------------------------------------------------------------
// Kernel 1: h = x @ W^T.  One thread per node row, single pass over all 64
// output channels (64 accumulators) so x is loaded exactly ONCE (32 LDG.128
// per thread).  W in smem, native [c][k] layout, read as float4 with
// warp-uniform addresses (broadcast, conflict-free).  FFMA-pipe bound.
// ---------------------------------------------------------------------------
__global__ __launch_bounds__(256) void gemm_kernel(
    const float* __restrict__ x,
    const float* __restrict__ W,
    int n)
{
    __shared__ float wsh[OUT_C * IN_C];   // 32 KB, [c][k]

    const int tid = threadIdx.x;
    for (int e = tid; e < OUT_C * IN_C; e += 256)
        wsh[e] = W[e];
    __syncthreads();

    const int r = blockIdx.x * 256 + tid;
    if (r >= n) return;

    const float4* xr = reinterpret_cast<const float4*>(x + (size_t)r * IN_C);
    const float4* w4 = reinterpret_cast<const float4*>(wsh);  // [c][k4]: c*32+k4

    float acc[OUT_C];
#pragma unroll
    for (int c = 0; c < OUT_C; c++) acc[c] = 0.0f;

#pragma unroll
    for (int kb = 0; kb < 4; kb++) {          // K in chunks of 32 floats
        float4 xv[8];
#pragma unroll
        for (int j = 0; j < 8; j++)
            xv[j] = __ldg(&xr[kb * 8 + j]);   // x loaded once per element

#pragma unroll
        for (int j = 0; j < 8; j++) {
            const float x0 = xv[j].x, x1 = xv[j].y, x2 = xv[j].z, x3 = xv[j].w;
#pragma unroll
            for (int c = 0; c < OUT_C; c++) {
                const float4 w = w4[c * 32 + kb * 8 + j];   // warp-uniform LDS
                acc[c] += x0 * w.x + x1 * w.y + x2 * w.z + x3 * w.w;
            }
        }
    }

    float4* out4 = reinterpret_cast<float4*>(g_h + (size_t)r * OUT_C);
#pragma unroll
    for (int c4 = 0; c4 < OUT_C / 4; c4++)
        out4[c4] = make_float4(acc[4 * c4], acc[4 * c4 + 1],
                               acc[4 * c4 + 2], acc[4 * c4 + 3]);
}

// ---------------------------------------------------------------------------
// Kernel 2: gather + lower-median over K=32.
// 256 threads/block = 4 nodes x 64 channels; warp = 32 consecutive channels
// of one node -> each neighbor gather touches one 128B line (L2-resident).
// Median: Batcher odd-even mergesort (63 CAS, REGULAR recursive wiring) on
// each half of 16, then 16th-smallest of the merge via max_i min(A[i],B[15-i]).
// ---------------------------------------------------------------------------
__device__ __forceinline__ void cas(float& a, float& b) {
    float lo = fminf(a, b);
    b = fmaxf(a, b);
    a = lo;
}

// Batcher odd-even mergesort, canonical iterative form; fully unrolled,
// all bounds/conditions constant-fold (63 comparators for n=16).
__device__ __forceinline__ void bsort16(float* v) {
#pragma unroll
    for (int p = 1; p < 16; p <<= 1) {
#pragma unroll
        for (int k = p; k >= 1; k >>= 1) {
#pragma unroll
            for (int j = (k & (p - 1)); j + k < 16; j += 2 * k) {
#pragma unroll
                for (int i = 0; i < k; i++) {
                    if (j + i + k < 16) {
                        if ((i + j) / (2 * p) == (i + j + k) / (2 * p))
                            cas(v[i + j], v[i + j + k]);
                    }
                }
            }
        }
    }
}

__global__ __launch_bounds__(256) void median_kernel(
    const int* __restrict__ nbrs,      // int32
    float* __restrict__ out,
    int n)
{
    __shared__ int snb[4 * KNBR];

    const int base = blockIdx.x * 4;
    const int tid = threadIdx.x;

    if (tid < 4 * KNBR) {
        int node = base + (tid >> 5);
        int idx = (node < n) ? nbrs[(size_t)node * KNBR + (tid & 31)] : 0;
        idx = max(0, min(idx, n - 1));   // defensive clamp
        snb[tid] = idx;
    }
    __syncthreads();

    const int ty = tid >> 6;   // node within block (0..3)
    const int tx = tid & 63;   // output channel
    const int node = base + ty;
    if (node >= n) return;

    float v[KNBR];
#pragma unroll
    for (int k = 0; k < KNBR; k++) {
        int idx = snb[ty * KNBR + k];            // smem broadcast
        v[k] = __ldg(&g_h[(size_t)idx * OUT_C + tx]);
    }

    bsort16(v);
    bsort16(v + 16);

    // 16th smallest (rank index 15) of the merge of two sorted 16-arrays
    float med = fminf(v[0], v[31]);
#pragma unroll
    for (int i = 1; i < 16; i++)
        med = fmaxf(med, fminf(v[i], v[31 - i]));

    out[(size_t)node * OUT_C + tx] = med;
}

// ---------------------------------------------------------------------------
// Profiling aid: pads launches/call to 5 so ncu's "-s 5 -c 1" capture lands
// on gemm_kernel (launch #6 = replay-1 position-1) instead of median_kernel.
// ---------------------------------------------------------------------------
__global__ void noop_kernel() {}

extern "C" void kernel_launch(void* const* d_in, const int* in_sizes, int n_in,
                              void* d_out, int out_size) {
    const float* x    = (const float*)d_in[0];
    const int*   nbrs = (const int*)d_in[1];
    const float* W    = (const float*)d_in[2];
    float*       out  = (float*)d_out;

    const int n = in_sizes[0] / IN_C;   // 100000

    gemm_kernel<<<(n + 255) / 256, 256>>>(x, W, n);
    median_kernel<<<(n + 3) / 4, 256>>>(nbrs, out, n);
    noop_kernel<<<1, 32>>>();
    noop_kernel<<<1, 32>>>();
    noop_kernel<<<1, 32>>>();
}

// round 8
// speedup vs baseline: 1.2101x; 1.2101x over previous
#include <cuda_runtime.h>
#include <cuda_bf16.h>
#include <cstdint>

// ---------------------------------------------------------------------------
// MedianConvolution: out[n,c] = lower_median_k( (x @ W^T)[nbrs[n,k], c] )
// N=100000, K=32, IN_C=128, OUT_C=64.  nbrs is int32 (JAX demotes int64).
// ---------------------------------------------------------------------------

#define N_NODES 100000
#define IN_C    128
#define OUT_C   64
#define KNBR    32

// gemm tile config
#define BM 128
#define BK 16
#define TM 8
#define TN 4
#define XPAD 4   // row strides must be multiples of 4 floats for float4 LDS
#define WPAD 4

// intermediate h = x @ W^T  (25.6 MB static device scratch — allocation-free)
__device__ float g_h[N_NODES * OUT_C];

// ---------------------------------------------------------------------------
// Kernel 1: h = x @ W^T.  2D block-tiled SGEMM.
// Block computes 128 rows x 64 cols; thread = 8x4 micro-tile (32 accs).
// xs[k][row] stride 132 (16B-aligned rows): compute reads are warp-uniform k
// -> 2 distinct 16B segments/warp (broadcast).  wt[k][c] stride 68: read
// addrs tx*16 cover all banks (conflict-free).  FFMA-bound.
// ---------------------------------------------------------------------------
__global__ __launch_bounds__(256) void gemm_kernel(
    const float* __restrict__ x,
    const float* __restrict__ W,
    int n)
{
    __shared__ float wt[IN_C][OUT_C + WPAD];   // 34.8 KB
    __shared__ float xs[BK][BM + XPAD];        // 8.4 KB

    const int tid = threadIdx.x;
    const int tx = tid & 15;                // col group: cols tx*4..+3
    const int ty = tid >> 4;                // row group: rows ty*8..+7
    const int rowBase = blockIdx.x * BM;

    // stage W transposed (one-time; bank conflicts here are negligible)
    for (int e = tid; e < OUT_C * IN_C; e += 256) {
        int c = e >> 7, k = e & 127;
        wt[k][c] = W[e];
    }

    float acc[TM][TN];
#pragma unroll
    for (int i = 0; i < TM; i++)
#pragma unroll
        for (int j = 0; j < TN; j++) acc[i][j] = 0.0f;

    for (int kb = 0; kb < IN_C / BK; kb++) {
        __syncthreads();   // first iter: covers W staging; later: xs reuse
        // stage x tile [128 rows][16 k]: 512 float4, 2 per thread
#pragma unroll
        for (int i = 0; i < 2; i++) {
            int e   = tid + i * 256;        // 0..511
            int row = e >> 2;               // 0..127
            int q   = e & 3;                // float4 within the 16-k chunk
            int grow = rowBase + row;
            float4 v = make_float4(0.f, 0.f, 0.f, 0.f);
            if (grow < n)
                v = __ldg(reinterpret_cast<const float4*>(
                        x + (size_t)grow * IN_C + kb * BK) + q);
            xs[q * 4 + 0][row] = v.x;
            xs[q * 4 + 1][row] = v.y;
            xs[q * 4 + 2][row] = v.z;
            xs[q * 4 + 3][row] = v.w;
        }
        __syncthreads();

#pragma unroll
        for (int k = 0; k < BK; k++) {
            float4 xa = *reinterpret_cast<const float4*>(&xs[k][ty * TM]);
            float4 xb = *reinterpret_cast<const float4*>(&xs[k][ty * TM + 4]);
            float4 wv = *reinterpret_cast<const float4*>(&wt[kb * BK + k][tx * TN]);
            const float xv[TM] = { xa.x, xa.y, xa.z, xa.w,
                                   xb.x, xb.y, xb.z, xb.w };
#pragma unroll
            for (int i = 0; i < TM; i++) {
                acc[i][0] += xv[i] * wv.x;
                acc[i][1] += xv[i] * wv.y;
                acc[i][2] += xv[i] * wv.z;
                acc[i][3] += xv[i] * wv.w;
            }
        }
    }

#pragma unroll
    for (int i = 0; i < TM; i++) {
        int grow = rowBase + ty * TM + i;
        if (grow < n) {
            float4* o = reinterpret_cast<float4*>(
                g_h + (size_t)grow * OUT_C + tx * TN);
            *o = make_float4(acc[i][0], acc[i][1], acc[i][2], acc[i][3]);
        }
    }
}

// ---------------------------------------------------------------------------
// Kernel 2: gather + lower-median over K=32.
// 256 threads/block = 4 nodes x 64 channels; warp = 32 consecutive channels
// of one node -> each neighbor gather touches one 128B line (L2-resident).
// Median: Batcher odd-even mergesort (63 CAS, regular recurrence) per half,
// then 16th-smallest of the merge via max_i min(A[i], B[15-i]): 283 alu ops.
// ---------------------------------------------------------------------------
__device__ __forceinline__ void cas(float& a, float& b) {
    float lo = fminf(a, b);
    b = fmaxf(a, b);
    a = lo;
}

__device__ __forceinline__ void bsort16(float* v) {
#pragma unroll
    for (int p = 1; p < 16; p <<= 1) {
#pragma unroll
        for (int k = p; k >= 1; k >>= 1) {
#pragma unroll
            for (int j = (k & (p - 1)); j + k < 16; j += 2 * k) {
#pragma unroll
                for (int i = 0; i < k; i++) {
                    if (j + i + k < 16) {
                        if ((i + j) / (2 * p) == (i + j + k) / (2 * p))
                            cas(v[i + j], v[i + j + k]);
                    }
                }
            }
        }
    }
}

__global__ __launch_bounds__(256) void median_kernel(
    const int* __restrict__ nbrs,      // int32
    float* __restrict__ out,
    int n)
{
    __shared__ int snb[4 * KNBR];

    const int base = blockIdx.x * 4;
    const int tid = threadIdx.x;

    if (tid < 4 * KNBR) {
        int node = base + (tid >> 5);
        int idx = (node < n) ? nbrs[(size_t)node * KNBR + (tid & 31)] : 0;
        idx = max(0, min(idx, n - 1));   // defensive clamp
        snb[tid] = idx;
    }
    __syncthreads();

    const int ty = tid >> 6;   // node within block (0..3)
    const int tx = tid & 63;   // output channel
    const int node = base + ty;
    if (node >= n) return;

    float v[KNBR];
#pragma unroll
    for (int k = 0; k < KNBR; k++) {
        int idx = snb[ty * KNBR + k];            // smem broadcast
        v[k] = __ldg(&g_h[(size_t)idx * OUT_C + tx]);
    }

    bsort16(v);
    bsort16(v + 16);

    // 16th smallest (rank index 15) of the merge of two sorted 16-arrays
    float med = fminf(v[0], v[31]);
#pragma unroll
    for (int i = 1; i < 16; i++)
        med = fmaxf(med, fminf(v[i], v[31 - i]));

    out[(size_t)node * OUT_C + tx] = med;
}

// ---------------------------------------------------------------------------
extern "C" void kernel_launch(void* const* d_in, const int* in_sizes, int n_in,
                              void* d_out, int out_size) {
    const float* x    = (const float*)d_in[0];
    const int*   nbrs = (const int*)d_in[1];
    const float* W    = (const float*)d_in[2];
    float*       out  = (float*)d_out;

    const int n = in_sizes[0] / IN_C;   // 100000

    gemm_kernel<<<(n + BM - 1) / BM, 256>>>(x, W, n);
    median_kernel<<<(n + 3) / 4, 256>>>(nbrs, out, n);
}

// round 9
// speedup vs baseline: 3.1651x; 2.6156x over previous
#include <cuda_runtime.h>
#include <cuda_bf16.h>
#include <cstdint>

// ---------------------------------------------------------------------------
// MedianConvolution: out[n,c] = lower_median_k( (x @ W^T)[nbrs[n,k], c] )
// N=100000, K=32, IN_C=128, OUT_C=64.  nbrs is int32 (JAX demotes int64).
// ---------------------------------------------------------------------------

#define N_NODES 100000
#define IN_C    128
#define OUT_C   64
#define KNBR    32

// gemm tile config
#define BM 128
#define BK 16
#define TM 8
#define TN 4
#define XPAD 4
#define WPAD 4

// intermediate h = x @ W^T  (25.6 MB static device scratch — allocation-free)
__device__ float g_h[N_NODES * OUT_C];

// ---------------------------------------------------------------------------
// Kernel 1: h = x @ W^T.  2D block-tiled SGEMM (measured: ~47us, FFMA floor,
// bit-exact vs reference).  DO NOT TOUCH.
// ---------------------------------------------------------------------------
__global__ __launch_bounds__(256) void gemm_kernel(
    const float* __restrict__ x,
    const float* __restrict__ W,
    int n)
{
    __shared__ float wt[IN_C][OUT_C + WPAD];   // 34.8 KB
    __shared__ float xs[BK][BM + XPAD];        // 8.4 KB

    const int tid = threadIdx.x;
    const int tx = tid & 15;                // col group: cols tx*4..+3
    const int ty = tid >> 4;                // row group: rows ty*8..+7
    const int rowBase = blockIdx.x * BM;

    for (int e = tid; e < OUT_C * IN_C; e += 256) {
        int c = e >> 7, k = e & 127;
        wt[k][c] = W[e];
    }

    float acc[TM][TN];
#pragma unroll
    for (int i = 0; i < TM; i++)
#pragma unroll
        for (int j = 0; j < TN; j++) acc[i][j] = 0.0f;

    for (int kb = 0; kb < IN_C / BK; kb++) {
        __syncthreads();
#pragma unroll
        for (int i = 0; i < 2; i++) {
            int e   = tid + i * 256;
            int row = e >> 2;
            int q   = e & 3;
            int grow = rowBase + row;
            float4 v = make_float4(0.f, 0.f, 0.f, 0.f);
            if (grow < n)
                v = __ldg(reinterpret_cast<const float4*>(
                        x + (size_t)grow * IN_C + kb * BK) + q);
            xs[q * 4 + 0][row] = v.x;
            xs[q * 4 + 1][row] = v.y;
            xs[q * 4 + 2][row] = v.z;
            xs[q * 4 + 3][row] = v.w;
        }
        __syncthreads();

#pragma unroll
        for (int k = 0; k < BK; k++) {
            float4 xa = *reinterpret_cast<const float4*>(&xs[k][ty * TM]);
            float4 xb = *reinterpret_cast<const float4*>(&xs[k][ty * TM + 4]);
            float4 wv = *reinterpret_cast<const float4*>(&wt[kb * BK + k][tx * TN]);
            const float xv[TM] = { xa.x, xa.y, xa.z, xa.w,
                                   xb.x, xb.y, xb.z, xb.w };
#pragma unroll
            for (int i = 0; i < TM; i++) {
                acc[i][0] += xv[i] * wv.x;
                acc[i][1] += xv[i] * wv.y;
                acc[i][2] += xv[i] * wv.z;
                acc[i][3] += xv[i] * wv.w;
            }
        }
    }

#pragma unroll
    for (int i = 0; i < TM; i++) {
        int grow = rowBase + ty * TM + i;
        if (grow < n) {
            float4* o = reinterpret_cast<float4*>(
                g_h + (size_t)grow * OUT_C + tx * TN);
            *o = make_float4(acc[i][0], acc[i][1], acc[i][2], acc[i][3]);
        }
    }
}

// ---------------------------------------------------------------------------
// Kernel 2: gather + lower-median over K=32.
// Median: EXPLICIT Batcher odd-even mergesort (63 comparators, all indices
// literal -> guaranteed register promotion) on each half of 16, then the
// 16th-smallest of the merge via max_i min(A[i], B[15-i]).  283 alu ops.
// ---------------------------------------------------------------------------
__device__ __forceinline__ void cas(float& a, float& b) {
    float lo = fminf(a, b);
    b = fmaxf(a, b);
    a = lo;
}

// Batcher odd-even mergesort, n=16, 63 comparators, explicit listing
// (generated from the canonical recurrence; layers L1..L10).
#define S(i,j) cas(v[i], v[j])
__device__ __forceinline__ void bsort16(float* v) {
    // L1
    S(0,1); S(2,3); S(4,5); S(6,7); S(8,9); S(10,11); S(12,13); S(14,15);
    // L2
    S(0,2); S(1,3); S(4,6); S(5,7); S(8,10); S(9,11); S(12,14); S(13,15);
    // L3
    S(1,2); S(5,6); S(9,10); S(13,14);
    // L4
    S(0,4); S(1,5); S(2,6); S(3,7); S(8,12); S(9,13); S(10,14); S(11,15);
    // L5
    S(2,4); S(3,5); S(10,12); S(11,13);
    // L6
    S(1,2); S(3,4); S(5,6); S(9,10); S(11,12); S(13,14);
    // L7
    S(0,8); S(1,9); S(2,10); S(3,11); S(4,12); S(5,13); S(6,14); S(7,15);
    // L8
    S(4,8); S(5,9); S(6,10); S(7,11);
    // L9
    S(2,4); S(3,5); S(6,8); S(7,9); S(10,12); S(11,13);
    // L10
    S(1,2); S(3,4); S(5,6); S(7,8); S(9,10); S(11,12); S(13,14);
}
#undef S

__global__ __launch_bounds__(256) void median_kernel(
    const int* __restrict__ nbrs,      // int32
    float* __restrict__ out,
    int n)
{
    __shared__ int snb[4 * KNBR];

    const int base = blockIdx.x * 4;
    const int tid = threadIdx.x;

    if (tid < 4 * KNBR) {
        int node = base + (tid >> 5);
        int idx = (node < n) ? nbrs[(size_t)node * KNBR + (tid & 31)] : 0;
        idx = max(0, min(idx, n - 1));   // defensive clamp
        snb[tid] = idx;
    }
    __syncthreads();

    const int ty = tid >> 6;   // node within block (0..3)
    const int tx = tid & 63;   // output channel
    const int node = base + ty;
    if (node >= n) return;

    float v[KNBR];
#pragma unroll
    for (int k = 0; k < KNBR; k++) {
        int idx = snb[ty * KNBR + k];            // smem broadcast
        v[k] = __ldg(&g_h[(size_t)idx * OUT_C + tx]);
    }

    bsort16(v);
    bsort16(v + 16);

    // 16th smallest (rank index 15) of the merge of two sorted 16-arrays
    float med = fminf(v[0], v[31]);
#pragma unroll
    for (int i = 1; i < 16; i++)
        med = fmaxf(med, fminf(v[i], v[31 - i]));

    out[(size_t)node * OUT_C + tx] = med;
}

// ---------------------------------------------------------------------------
extern "C" void kernel_launch(void* const* d_in, const int* in_sizes, int n_in,
                              void* d_out, int out_size) {
    const float* x    = (const float*)d_in[0];
    const int*   nbrs = (const int*)d_in[1];
    const float* W    = (const float*)d_in[2];
    float*       out  = (float*)d_out;

    const int n = in_sizes[0] / IN_C;   // 100000

    gemm_kernel<<<(n + BM - 1) / BM, 256>>>(x, W, n);
    median_kernel<<<(n + 3) / 4, 256>>>(nbrs, out, n);
}

// round 10
// speedup vs baseline: 4.9640x; 1.5684x over previous
#include <cuda_runtime.h>
#include <cuda_bf16.h>
#include <cuda_fp16.h>
#include <cstdint>

// ---------------------------------------------------------------------------
// MedianConvolution: out[n,c] = lower_median_k( (x @ W^T)[nbrs[n,k], c] )
// N=100000, K=32, IN_C=128, OUT_C=64.  nbrs is int32 (JAX demotes int64).
// h kept in fp16 (tolerance 1e-3, fp16 rel err ~5e-4); median network runs
// packed half2 = 2 channels per op on the alu pipe.
// ---------------------------------------------------------------------------

#define N_NODES 100000
#define IN_C    128
#define OUT_C   64
#define KNBR    32

// gemm tile config
#define BM 128
#define BK 16
#define TM 8
#define TN 4
#define XPAD 4
#define WPAD 4

// intermediate h = x @ W^T in fp16 (12.8 MB static scratch — allocation-free)
__device__ __align__(16) __half g_h[N_NODES * OUT_C];

// ---------------------------------------------------------------------------
// Kernel 1: h = x @ W^T.  2D block-tiled SGEMM (~47us, FFMA floor).
// Epilogue converts fp32 accumulators to fp16 (cvt hides in idle issue slots).
// ---------------------------------------------------------------------------
__global__ __launch_bounds__(256) void gemm_kernel(
    const float* __restrict__ x,
    const float* __restrict__ W,
    int n)
{
    __shared__ float wt[IN_C][OUT_C + WPAD];   // 34.8 KB
    __shared__ float xs[BK][BM + XPAD];        // 8.4 KB

    const int tid = threadIdx.x;
    const int tx = tid & 15;                // col group: cols tx*4..+3
    const int ty = tid >> 4;                // row group: rows ty*8..+7
    const int rowBase = blockIdx.x * BM;

    for (int e = tid; e < OUT_C * IN_C; e += 256) {
        int c = e >> 7, k = e & 127;
        wt[k][c] = W[e];
    }

    float acc[TM][TN];
#pragma unroll
    for (int i = 0; i < TM; i++)
#pragma unroll
        for (int j = 0; j < TN; j++) acc[i][j] = 0.0f;

    for (int kb = 0; kb < IN_C / BK; kb++) {
        __syncthreads();
#pragma unroll
        for (int i = 0; i < 2; i++) {
            int e   = tid + i * 256;
            int row = e >> 2;
            int q   = e & 3;
            int grow = rowBase + row;
            float4 v = make_float4(0.f, 0.f, 0.f, 0.f);
            if (grow < n)
                v = __ldg(reinterpret_cast<const float4*>(
                        x + (size_t)grow * IN_C + kb * BK) + q);
            xs[q * 4 + 0][row] = v.x;
            xs[q * 4 + 1][row] = v.y;
            xs[q * 4 + 2][row] = v.z;
            xs[q * 4 + 3][row] = v.w;
        }
        __syncthreads();

#pragma unroll
        for (int k = 0; k < BK; k++) {
            float4 xa = *reinterpret_cast<const float4*>(&xs[k][ty * TM]);
            float4 xb = *reinterpret_cast<const float4*>(&xs[k][ty * TM + 4]);
            float4 wv = *reinterpret_cast<const float4*>(&wt[kb * BK + k][tx * TN]);
            const float xv[TM] = { xa.x, xa.y, xa.z, xa.w,
                                   xb.x, xb.y, xb.z, xb.w };
#pragma unroll
            for (int i = 0; i < TM; i++) {
                acc[i][0] += xv[i] * wv.x;
                acc[i][1] += xv[i] * wv.y;
                acc[i][2] += xv[i] * wv.z;
                acc[i][3] += xv[i] * wv.w;
            }
        }
    }

#pragma unroll
    for (int i = 0; i < TM; i++) {
        int grow = rowBase + ty * TM + i;
        if (grow < n) {
            __half2 p0 = __floats2half2_rn(acc[i][0], acc[i][1]);
            __half2 p1 = __floats2half2_rn(acc[i][2], acc[i][3]);
            __half2* o = reinterpret_cast<__half2*>(
                g_h + (size_t)grow * OUT_C + tx * TN);
            o[0] = p0;
            o[1] = p1;
        }
    }
}

// ---------------------------------------------------------------------------
// Kernel 2: gather + lower-median over K=32, packed half2 (2 channels/thread).
// 256 threads/block = 8 nodes x 32 threads; warp = 32 channel-pairs of one
// node -> each neighbor gather is exactly one 128B line (L2-resident).
// Median: explicit Batcher odd-even mergesort (63 comparators) per half,
// then 16th-smallest of the merge via max_i min(A[i], B[15-i]).
// ---------------------------------------------------------------------------
__device__ __forceinline__ void cas2(__half2& a, __half2& b) {
    __half2 lo = __hmin2(a, b);
    b = __hmax2(a, b);
    a = lo;
}

// Batcher odd-even mergesort, n=16, 63 comparators, explicit listing.
#define S(i,j) cas2(v[i], v[j])
__device__ __forceinline__ void bsort16h(__half2* v) {
    // L1
    S(0,1); S(2,3); S(4,5); S(6,7); S(8,9); S(10,11); S(12,13); S(14,15);
    // L2
    S(0,2); S(1,3); S(4,6); S(5,7); S(8,10); S(9,11); S(12,14); S(13,15);
    // L3
    S(1,2); S(5,6); S(9,10); S(13,14);
    // L4
    S(0,4); S(1,5); S(2,6); S(3,7); S(8,12); S(9,13); S(10,14); S(11,15);
    // L5
    S(2,4); S(3,5); S(10,12); S(11,13);
    // L6
    S(1,2); S(3,4); S(5,6); S(9,10); S(11,12); S(13,14);
    // L7
    S(0,8); S(1,9); S(2,10); S(3,11); S(4,12); S(5,13); S(6,14); S(7,15);
    // L8
    S(4,8); S(5,9); S(6,10); S(7,11);
    // L9
    S(2,4); S(3,5); S(6,8); S(7,9); S(10,12); S(11,13);
    // L10
    S(1,2); S(3,4); S(5,6); S(7,8); S(9,10); S(11,12); S(13,14);
}
#undef S

__global__ __launch_bounds__(256) void median_kernel(
    const int* __restrict__ nbrs,      // int32
    float* __restrict__ out,
    int n)
{
    __shared__ int snb[8 * KNBR];

    const int base = blockIdx.x * 8;
    const int tid = threadIdx.x;

    {
        int node = base + (tid >> 5);
        int idx = (node < n) ? nbrs[(size_t)node * KNBR + (tid & 31)] : 0;
        idx = max(0, min(idx, n - 1));   // defensive clamp
        snb[tid] = idx;
    }
    __syncthreads();

    const int ty = tid >> 5;   // node within block (0..7)
    const int tx = tid & 31;   // channel-pair index (channels 2tx, 2tx+1)
    const int node = base + ty;
    if (node >= n) return;

    const __half2* h2 = reinterpret_cast<const __half2*>(g_h);

    __half2 v[KNBR];
#pragma unroll
    for (int k = 0; k < KNBR; k++) {
        int idx = snb[ty * KNBR + k];                 // smem broadcast
        v[k] = __ldg(&h2[(size_t)idx * (OUT_C / 2) + tx]);
    }

    bsort16h(v);
    bsort16h(v + 16);

    // 16th smallest (rank index 15) of the merge of two sorted 16-arrays,
    // computed independently in both half lanes
    __half2 med = __hmin2(v[0], v[31]);
#pragma unroll
    for (int i = 1; i < 16; i++)
        med = __hmax2(med, __hmin2(v[i], v[31 - i]));

    float2 f = __half22float2(med);
    float2* o = reinterpret_cast<float2*>(out + (size_t)node * OUT_C) + tx;
    *o = f;
}

// ---------------------------------------------------------------------------
extern "C" void kernel_launch(void* const* d_in, const int* in_sizes, int n_in,
                              void* d_out, int out_size) {
    const float* x    = (const float*)d_in[0];
    const int*   nbrs = (const int*)d_in[1];
    const float* W    = (const float*)d_in[2];
    float*       out  = (float*)d_out;

    const int n = in_sizes[0] / IN_C;   // 100000

    gemm_kernel<<<(n + BM - 1) / BM, 256>>>(x, W, n);
    median_kernel<<<(n + 7) / 8, 256>>>(nbrs, out, n);
}

// round 11
// speedup vs baseline: 5.0530x; 1.0179x over previous
#include <cuda_runtime.h>
#include <cuda_fp16.h>
#include <cstdint>

// ---------------------------------------------------------------------------
// MedianConvolution: out[n,c] = lower_median_k( (x @ W^T)[nbrs[n,k], c] )
// N=100000, K=32, IN_C=128, OUT_C=64.  nbrs is int32 (JAX demotes int64).
// h kept in fp16; median runs packed half2.  GEMM uses packed f32x2 FMA
// (FFMA2: 2 independent fp32 FMAs per issue slot, bit-identical results).
// ---------------------------------------------------------------------------

#define N_NODES 100000
#define IN_C    128
#define OUT_C   64
#define KNBR    32

// gemm tile config
#define BM 128
#define BK 16
#define TM 8
#define TN 4
#define XPAD 4
#define WPAD 4

// intermediate h = x @ W^T in fp16 (12.8 MB static scratch — allocation-free)
__device__ __align__(16) __half g_h[N_NODES * OUT_C];

typedef unsigned long long u64;

__device__ __forceinline__ u64 pk2(float a, float b) {
    u64 r;
    asm("mov.b64 %0, {%1, %2};" : "=l"(r) : "f"(a), "f"(b));
    return r;
}
__device__ __forceinline__ void upk2(u64 p, float& a, float& b) {
    asm("mov.b64 {%0, %1}, %2;" : "=f"(a), "=f"(b) : "l"(p));
}
// acc = x2 * w2 + acc, per-lane fp32 (FFMA2)
__device__ __forceinline__ void fma2(u64& acc, u64 x2, u64 w2) {
    asm("fma.rn.f32x2 %0, %1, %2, %0;" : "+l"(acc) : "l"(x2), "l"(w2));
}

// ---------------------------------------------------------------------------
// Kernel 1: h = x @ W^T.  2D block-tiled SGEMM, FFMA2 inner loop.
// Block = 128 rows x 64 cols; thread = 8x4 micro-tile as 16 f32x2 accs
// (row-pairs x 4 cols).  xs[k][row]: rows contiguous -> ulonglong2 LDS gives
// row-pairs pre-packed.  wt[k][c] read as float4; 4 (w,w) packs per k.
// ---------------------------------------------------------------------------
__global__ __launch_bounds__(256) void gemm_kernel(
    const float* __restrict__ x,
    const float* __restrict__ W,
    int n)
{
    __shared__ float wt[IN_C][OUT_C + WPAD];   // 34.8 KB
    __shared__ float xs[BK][BM + XPAD];        // 8.4 KB (row stride 528B, 16B-mult)

    const int tid = threadIdx.x;
    const int tx = tid & 15;                // col group: cols tx*4..+3
    const int ty = tid >> 4;                // row group: rows ty*8..+7
    const int rowBase = blockIdx.x * BM;

    for (int e = tid; e < OUT_C * IN_C; e += 256) {
        int c = e >> 7, k = e & 127;
        wt[k][c] = W[e];
    }

    u64 acc2[TM / 2][TN];                   // [row-pair][col]
#pragma unroll
    for (int i = 0; i < TM / 2; i++)
#pragma unroll
        for (int j = 0; j < TN; j++) acc2[i][j] = 0ull;

    for (int kb = 0; kb < IN_C / BK; kb++) {
        __syncthreads();   // first iter: covers W staging; later: xs reuse
#pragma unroll
        for (int i = 0; i < 2; i++) {
            int e   = tid + i * 256;
            int row = e >> 2;
            int q   = e & 3;
            int grow = rowBase + row;
            float4 v = make_float4(0.f, 0.f, 0.f, 0.f);
            if (grow < n)
                v = __ldg(reinterpret_cast<const float4*>(
                        x + (size_t)grow * IN_C + kb * BK) + q);
            xs[q * 4 + 0][row] = v.x;
            xs[q * 4 + 1][row] = v.y;
            xs[q * 4 + 2][row] = v.z;
            xs[q * 4 + 3][row] = v.w;
        }
        __syncthreads();

#pragma unroll
        for (int k = 0; k < BK; k++) {
            // two row-pair packs per LDS.128, already adjacent in xs
            const ulonglong2 xA =
                *reinterpret_cast<const ulonglong2*>(&xs[k][ty * TM]);
            const ulonglong2 xB =
                *reinterpret_cast<const ulonglong2*>(&xs[k][ty * TM + 4]);
            const float4 wv =
                *reinterpret_cast<const float4*>(&wt[kb * BK + k][tx * TN]);

            const u64 xp[TM / 2] = { xA.x, xA.y, xB.x, xB.y };
            const u64 w2[TN] = { pk2(wv.x, wv.x), pk2(wv.y, wv.y),
                                 pk2(wv.z, wv.z), pk2(wv.w, wv.w) };
#pragma unroll
            for (int i = 0; i < TM / 2; i++) {
                fma2(acc2[i][0], xp[i], w2[0]);
                fma2(acc2[i][1], xp[i], w2[1]);
                fma2(acc2[i][2], xp[i], w2[2]);
                fma2(acc2[i][3], xp[i], w2[3]);
            }
        }
    }

    // epilogue: unpack row-pairs, convert to fp16, store
#pragma unroll
    for (int i = 0; i < TM / 2; i++) {
        float lo[TN], hi[TN];
#pragma unroll
        for (int c = 0; c < TN; c++) upk2(acc2[i][c], lo[c], hi[c]);

        int r0 = rowBase + ty * TM + 2 * i;
        if (r0 < n) {
            __half2* o = reinterpret_cast<__half2*>(
                g_h + (size_t)r0 * OUT_C + tx * TN);
            o[0] = __floats2half2_rn(lo[0], lo[1]);
            o[1] = __floats2half2_rn(lo[2], lo[3]);
        }
        int r1 = r0 + 1;
        if (r1 < n) {
            __half2* o = reinterpret_cast<__half2*>(
                g_h + (size_t)r1 * OUT_C + tx * TN);
            o[0] = __floats2half2_rn(hi[0], hi[1]);
            o[1] = __floats2half2_rn(hi[2], hi[3]);
        }
    }
}

// ---------------------------------------------------------------------------
// Kernel 2: gather + lower-median over K=32, packed half2 (2 channels/thread).
// 256 threads/block = 8 nodes x 32 threads; warp = 32 channel-pairs of one
// node -> each neighbor gather is exactly one 128B line (L2-resident).
// Median: explicit Batcher odd-even mergesort (63 comparators) per half,
// then 16th-smallest of the merge via max_i min(A[i], B[15-i]).
// Measured 78.4us, alu-bound.  DO NOT TOUCH.
// ---------------------------------------------------------------------------
__device__ __forceinline__ void cas2(__half2& a, __half2& b) {
    __half2 lo = __hmin2(a, b);
    b = __hmax2(a, b);
    a = lo;
}

#define S(i,j) cas2(v[i], v[j])
__device__ __forceinline__ void bsort16h(__half2* v) {
    // L1
    S(0,1); S(2,3); S(4,5); S(6,7); S(8,9); S(10,11); S(12,13); S(14,15);
    // L2
    S(0,2); S(1,3); S(4,6); S(5,7); S(8,10); S(9,11); S(12,14); S(13,15);
    // L3
    S(1,2); S(5,6); S(9,10); S(13,14);
    // L4
    S(0,4); S(1,5); S(2,6); S(3,7); S(8,12); S(9,13); S(10,14); S(11,15);
    // L5
    S(2,4); S(3,5); S(10,12); S(11,13);
    // L6
    S(1,2); S(3,4); S(5,6); S(9,10); S(11,12); S(13,14);
    // L7
    S(0,8); S(1,9); S(2,10); S(3,11); S(4,12); S(5,13); S(6,14); S(7,15);
    // L8
    S(4,8); S(5,9); S(6,10); S(7,11);
    // L9
    S(2,4); S(3,5); S(6,8); S(7,9); S(10,12); S(11,13);
    // L10
    S(1,2); S(3,4); S(5,6); S(7,8); S(9,10); S(11,12); S(13,14);
}
#undef S

__global__ __launch_bounds__(256) void median_kernel(
    const int* __restrict__ nbrs,      // int32
    float* __restrict__ out,
    int n)
{
    __shared__ int snb[8 * KNBR];

    const int base = blockIdx.x * 8;
    const int tid = threadIdx.x;

    {
        int node = base + (tid >> 5);
        int idx = (node < n) ? nbrs[(size_t)node * KNBR + (tid & 31)] : 0;
        idx = max(0, min(idx, n - 1));   // defensive clamp
        snb[tid] = idx;
    }
    __syncthreads();

    const int ty = tid >> 5;   // node within block (0..7)
    const int tx = tid & 31;   // channel-pair index (channels 2tx, 2tx+1)
    const int node = base + ty;
    if (node >= n) return;

    const __half2* h2 = reinterpret_cast<const __half2*>(g_h);

    __half2 v[KNBR];
#pragma unroll
    for (int k = 0; k < KNBR; k++) {
        int idx = snb[ty * KNBR + k];                 // smem broadcast
        v[k] = __ldg(&h2[(size_t)idx * (OUT_C / 2) + tx]);
    }

    bsort16h(v);
    bsort16h(v + 16);

    // 16th smallest (rank index 15) of the merge of two sorted 16-arrays,
    // computed independently in both half lanes
    __half2 med = __hmin2(v[0], v[31]);
#pragma unroll
    for (int i = 1; i < 16; i++)
        med = __hmax2(med, __hmin2(v[i], v[31 - i]));

    float2 f = __half22float2(med);
    float2* o = reinterpret_cast<float2*>(out + (size_t)node * OUT_C) + tx;
    *o = f;
}

// ---------------------------------------------------------------------------
extern "C" void kernel_launch(void* const* d_in, const int* in_sizes, int n_in,
                              void* d_out, int out_size) {
    const float* x    = (const float*)d_in[0];
    const int*   nbrs = (const int*)d_in[1];
    const float* W    = (const float*)d_in[2];
    float*       out  = (float*)d_out;

    const int n = in_sizes[0] / IN_C;   // 100000

    gemm_kernel<<<(n + BM - 1) / BM, 256>>>(x, W, n);
    median_kernel<<<(n + 7) / 8, 256>>>(nbrs, out, n);
}